// round 8
// baseline (speedup 1.0000x reference)
#include <cuda_runtime.h>
#include <cuda_bf16.h>
#include <cstdint>

#define NMAX 100000
#define EMAX 1700000
#define Dd 100
#define KDATA 200
#define NP 104            // padded output cols (13 x n8)
#define KP 216            // smem k-stride (208 data+pad, conflict-free for ldmatrix)
#define NTHREADS 256
#define SCAN_B 1024

__device__ float g_agg[(size_t)NMAX * Dd];
__device__ float g_feat[(size_t)NMAX * Dd];
__device__ int   g_deg[NMAX];
__device__ int   g_off[NMAX + 1];
__device__ int   g_cur[NMAX];
__device__ int   g_csr[EMAX];
__device__ int   g_bsum[(NMAX + SCAN_B - 1) / SCAN_B];
__device__ __nv_bfloat16 g_Bhi[3][NP * KP];   // [set][n*KP + k], k-contiguous
__device__ __nv_bfloat16 g_Blo[3][NP * KP];

// ---------------- CSR build: histogram -> scan -> scatter ----------------

__global__ void hist_kernel(const int* __restrict__ dst, int* deg, int nE) {
    int e = blockIdx.x * blockDim.x + threadIdx.x;
    if (e < nE) atomicAdd(deg + __ldg(dst + e), 1);
}

__global__ void scanA_kernel(const int* __restrict__ deg, int* scanOut,
                             int* bsum, int n) {
    __shared__ int sm[SCAN_B];
    int i = blockIdx.x * SCAN_B + threadIdx.x;
    int v = (i < n) ? deg[i] : 0;
    sm[threadIdx.x] = v;
    __syncthreads();
    for (int o = 1; o < SCAN_B; o <<= 1) {
        int t = (threadIdx.x >= o) ? sm[threadIdx.x - o] : 0;
        __syncthreads();
        sm[threadIdx.x] += t;
        __syncthreads();
    }
    if (i < n) scanOut[i] = sm[threadIdx.x];
    if (threadIdx.x == SCAN_B - 1) bsum[blockIdx.x] = sm[SCAN_B - 1];
}

__global__ void scanB_kernel(int* bsum, int nb) {
    int lane = threadIdx.x;
    int carry = 0;
    for (int base = 0; base < nb; base += 32) {
        int i = base + lane;
        int orig = (i < nb) ? bsum[i] : 0;
        int v = orig;
        #pragma unroll
        for (int o = 1; o < 32; o <<= 1) {
            int t = __shfl_up_sync(0xffffffffu, v, o);
            if (lane >= o) v += t;
        }
        if (i < nb) bsum[i] = carry + (v - orig);
        carry += __shfl_sync(0xffffffffu, v, 31);
    }
}

__global__ void scanC_kernel(const int* __restrict__ scanIn,
                             const int* __restrict__ bsum,
                             const int* __restrict__ deg,
                             int* off, int* cur, int n) {
    int i = blockIdx.x * SCAN_B + threadIdx.x;
    if (i < n) {
        int incl = scanIn[i] + bsum[blockIdx.x];
        off[i + 1] = incl;
        cur[i] = incl - deg[i];
    }
    if (i == 0) off[0] = 0;
}

__global__ void scatter_kernel(const int* __restrict__ src,
                               const int* __restrict__ dst,
                               int* cur, int* csr, int nE) {
    int e = blockIdx.x * blockDim.x + threadIdx.x;
    if (e >= nE) return;
    int pos = atomicAdd(cur + __ldg(dst + e), 1);
    csr[pos] = __ldg(src + e);
}

// ---------------- Gather aggregation: mean of neighbor rows ----------------

__global__ void gather_kernel(const float* __restrict__ xin,
                              const int* __restrict__ csr,
                              const int* __restrict__ off,
                              float* __restrict__ aggOut, int n)
{
    int node = blockIdx.x * 8 + (threadIdx.x >> 5);
    int lane = threadIdx.x & 31;
    if (node >= n) return;
    int s0 = __ldg(off + node), s1 = __ldg(off + node + 1);
    float4 acc = make_float4(0.f, 0.f, 0.f, 0.f);
    int j = s0;
    int idx = (j < s1) ? __ldg(csr + j) : 0;
    while (j < s1) {
        int nidx = (j + 1 < s1) ? __ldg(csr + j + 1) : 0;
        if (lane < 25) {
            float4 v = __ldg(reinterpret_cast<const float4*>(
                    xin + (size_t)idx * Dd) + lane);
            acc.x += v.x; acc.y += v.y; acc.z += v.z; acc.w += v.w;
        }
        idx = nidx;
        j++;
    }
    if (lane < 25) {
        float inv = (s1 > s0) ? 1.0f / (float)(s1 - s0) : 0.f;
        acc.x *= inv; acc.y *= inv; acc.z *= inv; acc.w *= inv;
        reinterpret_cast<float4*>(aggOut + (size_t)node * Dd)[lane] = acc;
    }
}

// ---------------- Weight prep: fp32 W -> padded, transposed bf16 hi/lo ----------------
__global__ void prep_kernel(const float* __restrict__ Wsa, const float* __restrict__ Wsr,
                            const float* __restrict__ Wma, const float* __restrict__ Wmr,
                            const float* __restrict__ Wva, const float* __restrict__ Wvr)
{
    int i = blockIdx.x * blockDim.x + threadIdx.x;
    if (i >= 3 * NP * KP) return;
    int s = i / (NP * KP);
    int rem = i - s * (NP * KP);
    int nIdx = rem / KP;
    int k = rem - nIdx * KP;
    const float* Wa = (s == 0) ? Wsa : (s == 1) ? Wma : Wva;
    const float* Wr = (s == 0) ? Wsr : (s == 1) ? Wmr : Wvr;
    float v = 0.f;
    if (nIdx < Dd && k < KDATA)
        v = (k < Dd) ? __ldg(Wa + k * Dd + nIdx) : __ldg(Wr + (k - Dd) * Dd + nIdx);
    __nv_bfloat16 h = __float2bfloat16(v);
    __nv_bfloat16 l = __float2bfloat16(v - __bfloat162float(h));
    g_Bhi[s][rem] = h;
    g_Blo[s][rem] = l;
}

// ---------------- Tensor-core layer (mma.sync bf16 3-term split) ----------------
// CTA: 128 rows x 104 cols. 8 warps, warp w does rows [16w, 16w+16).
// Per k-step: load Ahi/Alo frags once, 13 Bhi frags -> 26 MMAs, 13 Blo frags -> 13 MMAs.
__global__ void __launch_bounds__(NTHREADS)
layer_mma(const float* __restrict__ agg, const float* __restrict__ root,
          const __nv_bfloat16* __restrict__ Bhi0, const __nv_bfloat16* __restrict__ Blo0,
          const float* __restrict__ bias0,
          const __nv_bfloat16* __restrict__ Bhi1, const __nv_bfloat16* __restrict__ Blo1,
          const float* __restrict__ bias1,
          float* __restrict__ out, int n, int doRelu)
{
    extern __shared__ char smraw[];
    float* sbias = reinterpret_cast<float*>(smraw);                    // 104 floats
    __nv_bfloat16* sA = reinterpret_cast<__nv_bfloat16*>(smraw + 512);
    __nv_bfloat16* Ahi = sA;
    __nv_bfloat16* Alo = Ahi + 128 * KP;
    __nv_bfloat16* Bhi = Alo + 128 * KP;
    __nv_bfloat16* Blo = Bhi + NP * KP;

    const __nv_bfloat16* gBhi = blockIdx.y ? Bhi1 : Bhi0;
    const __nv_bfloat16* gBlo = blockIdx.y ? Blo1 : Blo0;
    const float* gb = blockIdx.y ? bias1 : bias0;
    out += (size_t)blockIdx.y * n * Dd;

    const int tid = threadIdx.x;
    const int base = blockIdx.x * 128;

    // Stage B (bf16, already padded/transposed).
    {
        const float4* sh = reinterpret_cast<const float4*>(gBhi);
        const float4* sl = reinterpret_cast<const float4*>(gBlo);
        float4* dh = reinterpret_cast<float4*>(Bhi);
        float4* dl = reinterpret_cast<float4*>(Blo);
        for (int i = tid; i < (NP * KP * 2) / 16; i += NTHREADS) {
            dh[i] = __ldg(sh + i);
            dl[i] = __ldg(sl + i);
        }
    }
    if (tid < NP) sbias[tid] = (tid < Dd) ? __ldg(gb + tid) : 0.f;

    // Stage A: split fp32 [agg(100) | root(100)] into bf16 hi/lo.
    for (int idx = tid; idx < 128 * 50; idx += NTHREADS) {
        int r = idx / 50, q = idx - r * 50;
        int node = base + r;
        float4 v = make_float4(0.f, 0.f, 0.f, 0.f);
        if (node < n)
            v = (q < 25) ? __ldg(reinterpret_cast<const float4*>(
                                 agg + (size_t)node * Dd) + q)
                         : __ldg(reinterpret_cast<const float4*>(
                                 root + (size_t)node * Dd) + (q - 25));
        int kb = (q < 25) ? q * 4 : 100 + (q - 25) * 4;
        __nv_bfloat162 h01 = __floats2bfloat162_rn(v.x, v.y);
        __nv_bfloat162 h23 = __floats2bfloat162_rn(v.z, v.w);
        float2 f01 = __bfloat1622float2(h01);
        float2 f23 = __bfloat1622float2(h23);
        __nv_bfloat162 l01 = __floats2bfloat162_rn(v.x - f01.x, v.y - f01.y);
        __nv_bfloat162 l23 = __floats2bfloat162_rn(v.z - f23.x, v.w - f23.y);
        uint32_t* dh = reinterpret_cast<uint32_t*>(Ahi + r * KP + kb);
        uint32_t* dl = reinterpret_cast<uint32_t*>(Alo + r * KP + kb);
        dh[0] = *reinterpret_cast<uint32_t*>(&h01);
        dh[1] = *reinterpret_cast<uint32_t*>(&h23);
        dl[0] = *reinterpret_cast<uint32_t*>(&l01);
        dl[1] = *reinterpret_cast<uint32_t*>(&l23);
    }
    // Zero A pad cols k=200..207.
    for (int i = tid; i < 128 * 4; i += NTHREADS) {
        int r = i >> 2, c = i & 3;
        reinterpret_cast<uint32_t*>(Ahi)[r * (KP / 2) + 100 + c] = 0u;
        reinterpret_cast<uint32_t*>(Alo)[r * (KP / 2) + 100 + c] = 0u;
    }
    __syncthreads();

    const int lane = tid & 31;
    const int m0 = (tid >> 5) * 16;

    float acc[13][4];
    #pragma unroll
    for (int t = 0; t < 13; t++)
        acc[t][0] = acc[t][1] = acc[t][2] = acc[t][3] = 0.f;

    const int arow = m0 + (lane & 15);
    const int akoff = (lane >> 4) << 3;
    const int brow = lane & 7;
    const int bkoff = ((lane >> 3) & 1) << 3;

    #pragma unroll 1
    for (int ks = 0; ks < 13; ks++) {
        int k0 = ks * 16;
        uint32_t ah[4], al[4];
        {
            uint32_t addr = (uint32_t)__cvta_generic_to_shared(
                Ahi + arow * KP + k0 + akoff);
            asm volatile(
                "ldmatrix.sync.aligned.m8n8.x4.shared.b16 {%0,%1,%2,%3}, [%4];"
                : "=r"(ah[0]), "=r"(ah[1]), "=r"(ah[2]), "=r"(ah[3]) : "r"(addr));
        }
        {
            uint32_t addr = (uint32_t)__cvta_generic_to_shared(
                Alo + arow * KP + k0 + akoff);
            asm volatile(
                "ldmatrix.sync.aligned.m8n8.x4.shared.b16 {%0,%1,%2,%3}, [%4];"
                : "=r"(al[0]), "=r"(al[1]), "=r"(al[2]), "=r"(al[3]) : "r"(addr));
        }

        uint32_t bf[13][2];
        #pragma unroll
        for (int nt = 0; nt < 13; nt++) {
            uint32_t baddr = (uint32_t)__cvta_generic_to_shared(
                Bhi + (nt * 8 + brow) * KP + k0 + bkoff);
            asm volatile(
                "ldmatrix.sync.aligned.m8n8.x2.shared.b16 {%0,%1}, [%2];"
                : "=r"(bf[nt][0]), "=r"(bf[nt][1]) : "r"(baddr));
        }
        #pragma unroll
        for (int nt = 0; nt < 13; nt++)
            asm volatile(
                "mma.sync.aligned.m16n8k16.row.col.f32.bf16.bf16.f32 "
                "{%0,%1,%2,%3}, {%4,%5,%6,%7}, {%8,%9}, {%0,%1,%2,%3};"
                : "+f"(acc[nt][0]), "+f"(acc[nt][1]),
                  "+f"(acc[nt][2]), "+f"(acc[nt][3])
                : "r"(ah[0]), "r"(ah[1]), "r"(ah[2]), "r"(ah[3]),
                  "r"(bf[nt][0]), "r"(bf[nt][1]));
        #pragma unroll
        for (int nt = 0; nt < 13; nt++)
            asm volatile(
                "mma.sync.aligned.m16n8k16.row.col.f32.bf16.bf16.f32 "
                "{%0,%1,%2,%3}, {%4,%5,%6,%7}, {%8,%9}, {%0,%1,%2,%3};"
                : "+f"(acc[nt][0]), "+f"(acc[nt][1]),
                  "+f"(acc[nt][2]), "+f"(acc[nt][3])
                : "r"(al[0]), "r"(al[1]), "r"(al[2]), "r"(al[3]),
                  "r"(bf[nt][0]), "r"(bf[nt][1]));
        #pragma unroll
        for (int nt = 0; nt < 13; nt++) {
            uint32_t baddr = (uint32_t)__cvta_generic_to_shared(
                Blo + (nt * 8 + brow) * KP + k0 + bkoff);
            asm volatile(
                "ldmatrix.sync.aligned.m8n8.x2.shared.b16 {%0,%1}, [%2];"
                : "=r"(bf[nt][0]), "=r"(bf[nt][1]) : "r"(baddr));
        }
        #pragma unroll
        for (int nt = 0; nt < 13; nt++)
            asm volatile(
                "mma.sync.aligned.m16n8k16.row.col.f32.bf16.bf16.f32 "
                "{%0,%1,%2,%3}, {%4,%5,%6,%7}, {%8,%9}, {%0,%1,%2,%3};"
                : "+f"(acc[nt][0]), "+f"(acc[nt][1]),
                  "+f"(acc[nt][2]), "+f"(acc[nt][3])
                : "r"(ah[0]), "r"(ah[1]), "r"(ah[2]), "r"(ah[3]),
                  "r"(bf[nt][0]), "r"(bf[nt][1]));
    }

    // Epilogue: bias (+ReLU), store.
    int row0 = base + m0 + (lane >> 2);
    int row1 = row0 + 8;
    #pragma unroll
    for (int nt = 0; nt < 13; nt++) {
        int col0 = nt * 8 + ((lane & 3) << 1);
        if (col0 >= Dd) continue;
        float bv0 = sbias[col0], bv1 = sbias[col0 + 1];
        float v00 = acc[nt][0] + bv0, v01 = acc[nt][1] + bv1;
        float v10 = acc[nt][2] + bv0, v11 = acc[nt][3] + bv1;
        if (doRelu) {
            v00 = fmaxf(v00, 0.f); v01 = fmaxf(v01, 0.f);
            v10 = fmaxf(v10, 0.f); v11 = fmaxf(v11, 0.f);
        }
        if (row0 < n)
            *reinterpret_cast<float2*>(out + (size_t)row0 * Dd + col0) =
                make_float2(v00, v01);
        if (row1 < n)
            *reinterpret_cast<float2*>(out + (size_t)row1 * Dd + col0) =
                make_float2(v10, v11);
    }
}

extern "C" void kernel_launch(void* const* d_in, const int* in_sizes, int n_in,
                              void* d_out, int out_size)
{
    const float* x   = (const float*)d_in[0];
    const int*   ei  = (const int*)d_in[1];
    const float* Wsa = (const float*)d_in[3];
    const float* Wsr = (const float*)d_in[4];
    const float* bs_ = (const float*)d_in[5];
    const float* Wma = (const float*)d_in[6];
    const float* Wmr = (const float*)d_in[7];
    const float* bm  = (const float*)d_in[8];
    const float* Wva = (const float*)d_in[9];
    const float* Wvr = (const float*)d_in[10];
    const float* bv  = (const float*)d_in[11];

    int n  = in_sizes[0] / Dd;
    int nE = in_sizes[1] / 2;
    const int* src  = ei;
    const int* dstp = ei + nE;

    float *agg, *feat;
    int *deg, *off, *cur, *csr, *bsum;
    __nv_bfloat16 *bhiBase, *bloBase;
    cudaGetSymbolAddress((void**)&agg,  g_agg);
    cudaGetSymbolAddress((void**)&feat, g_feat);
    cudaGetSymbolAddress((void**)&deg,  g_deg);
    cudaGetSymbolAddress((void**)&off,  g_off);
    cudaGetSymbolAddress((void**)&cur,  g_cur);
    cudaGetSymbolAddress((void**)&csr,  g_csr);
    cudaGetSymbolAddress((void**)&bsum, g_bsum);
    cudaGetSymbolAddress((void**)&bhiBase, g_Bhi);
    cudaGetSymbolAddress((void**)&bloBase, g_Blo);

    size_t smem = 512 + (size_t)(2 * 128 + 2 * NP) * KP * sizeof(__nv_bfloat16);
    static bool attrSet = false;
    if (!attrSet) {
        cudaFuncSetAttribute(layer_mma,
                             cudaFuncAttributeMaxDynamicSharedMemorySize, (int)smem);
        attrSet = true;
    }

    // Weight prep (bf16 hi/lo, padded+transposed)
    prep_kernel<<<(3 * NP * KP + 255) / 256, 256>>>(Wsa, Wsr, Wma, Wmr, Wva, Wvr);

    // CSR build
    int nb = (n + SCAN_B - 1) / SCAN_B;
    cudaMemsetAsync(deg, 0, (size_t)n * sizeof(int));
    hist_kernel<<<(nE + 255) / 256, 256>>>(dstp, deg, nE);
    scanA_kernel<<<nb, SCAN_B>>>(deg, cur, bsum, n);
    scanB_kernel<<<1, 32>>>(bsum, nb);
    scanC_kernel<<<nb, SCAN_B>>>(cur, bsum, deg, off, cur, n);
    scatter_kernel<<<(nE + 255) / 256, 256>>>(src, dstp, cur, csr, nE);

    // Layer 1
    int gatherBlocks = (n + 7) / 8;
    gather_kernel<<<gatherBlocks, 256>>>(x, csr, off, agg, n);

    int rowBlocks = (n + 127) / 128;
    layer_mma<<<dim3(rowBlocks, 1), NTHREADS, smem>>>(
        agg, x, bhiBase, bloBase, bs_,
        bhiBase, bloBase, bs_, feat, n, 1);

    // Layers 2+3 (shared aggregation over feat)
    gather_kernel<<<gatherBlocks, 256>>>(feat, csr, off, agg, n);

    float* outp = (float*)d_out;
    layer_mma<<<dim3(rowBlocks, 2), NTHREADS, smem>>>(
        agg, feat,
        bhiBase + (size_t)1 * NP * KP, bloBase + (size_t)1 * NP * KP, bm,
        bhiBase + (size_t)2 * NP * KP, bloBase + (size_t)2 * NP * KP, bv,
        outp, n, 0);
}